// round 17
// baseline (speedup 1.0000x reference)
#include <cuda_runtime.h>
#include <cuda_bf16.h>
#include <cstdint>

// out[i] = softmax((x2[i] @ v1^T)/1000) @ x2[i],  v1 = x1@W.T + b,  N=384.
// P = 1/384 + delta  ->  out = colsum(x2[i])/384 + delta @ x2[i].
// GEMMs: mma.sync m16n8k16 bf16 (R15/R16 geometry).
// R17: the fp32->bf16 convert of this CTA's 128 rows is software-pipelined INTO
//      GEMM1 (chunk kc body converts chunk kc+2's columns), hiding its DRAM
//      latency under the MMA stream. Colsum via warp butterfly + smem atomics.

constexpr int N = 384;
constexpr float SCALE_INV = 1.0f / 1000.0f;
constexpr float INV_N = 1.0f / 384.0f;

constexpr int QS = 392;   // row stride (halves): 384 + 8 pad (sQ and g_xp)
constexpr int BS = 24;    // GEMM1 B row stride (halves): 16 + 8 pad (g_v1p)
constexpr int VS = 392;   // GEMM2 B row stride (halves) (= g_xp row stride)

constexpr int SQ_BYTES = 128 * QS * 2;        // 100352
constexpr int BUF_B    = 18432;               // v1 chunk 18432B; V chunk 12544B fits
constexpr int OFF_BUF  = SQ_BYTES;
constexpr int OFF_SROW = OFF_BUF + 3 * BUF_B;            // 155648
constexpr int OFF_CS   = OFF_SROW + 512 * 4;             // 157696
constexpr int SMEM_ATTN = OFF_CS + 384 * 4;              // 159232

__device__ __align__(1024) __nv_bfloat16 g_xp[(size_t)N * N * QS];   // x2 bf16 image, 784B rows
__device__ __align__(1024) __nv_bfloat16 g_v1p[24 * N * BS];         // v1 K16-chunks, 48B rows
__device__ float g_cs3[(size_t)N * 3 * N];                           // per-CTA colsum partials
__device__ int g_flag[N];                                            // convert-done counters

// ---------------------------------------------------------------------------
__device__ __forceinline__ uint32_t smem_u32(const void* p) {
    uint32_t a;
    asm("{ .reg .u64 t; cvta.to.shared.u64 t, %1; cvt.u32.u64 %0, t; }" : "=r"(a) : "l"(p));
    return a;
}
__device__ __forceinline__ void ldm4(uint32_t* r, uint32_t addr) {
    asm volatile("ldmatrix.sync.aligned.m8n8.x4.shared.b16 {%0,%1,%2,%3},[%4];"
                 : "=r"(r[0]), "=r"(r[1]), "=r"(r[2]), "=r"(r[3]) : "r"(addr));
}
__device__ __forceinline__ void ldm4t(uint32_t* r, uint32_t addr) {
    asm volatile("ldmatrix.sync.aligned.m8n8.x4.trans.shared.b16 {%0,%1,%2,%3},[%4];"
                 : "=r"(r[0]), "=r"(r[1]), "=r"(r[2]), "=r"(r[3]) : "r"(addr));
}
__device__ __forceinline__ void mma16816(float* d, const uint32_t* a, uint32_t b0, uint32_t b1) {
    asm volatile("mma.sync.aligned.m16n8k16.row.col.f32.bf16.bf16.f32 "
                 "{%0,%1,%2,%3},{%4,%5,%6,%7},{%8,%9},{%0,%1,%2,%3};"
                 : "+f"(d[0]), "+f"(d[1]), "+f"(d[2]), "+f"(d[3])
                 : "r"(a[0]), "r"(a[1]), "r"(a[2]), "r"(a[3]), "r"(b0), "r"(b1));
}
__device__ __forceinline__ uint32_t bf2_pack(float a, float b) {
    __nv_bfloat162 h = __floats2bfloat162_rn(a, b);
    return *reinterpret_cast<uint32_t*>(&h);
}
__device__ __forceinline__ void bulk_cp(uint32_t dst, const void* src, uint32_t bytes,
                                        uint32_t mbar) {
    asm volatile("cp.async.bulk.shared::cluster.global.mbarrier::complete_tx::bytes "
                 "[%0], [%1], %2, [%3];"
                 :: "r"(dst), "l"(src), "r"(bytes), "r"(mbar) : "memory");
}
__device__ __forceinline__ void mbar_init(uint32_t mb, uint32_t cnt) {
    asm volatile("mbarrier.init.shared.b64 [%0], %1;" :: "r"(mb), "r"(cnt) : "memory");
}
__device__ __forceinline__ void mbar_expect_tx(uint32_t mb, uint32_t bytes) {
    asm volatile("mbarrier.arrive.expect_tx.shared.b64 _, [%0], %1;"
                 :: "r"(mb), "r"(bytes) : "memory");
}
__device__ __forceinline__ void mbar_wait(uint32_t mb, uint32_t parity) {
    asm volatile(
        "{\n .reg .pred P;\n"
        "W_%=:\n mbarrier.try_wait.parity.shared.b64 P, [%0], %1;\n"
        " @P bra.uni D_%=;\n bra.uni W_%=;\nD_%=:\n}"
        :: "r"(mb), "r"(parity) : "memory");
}

// ---------------------------------------------------------------------------
// linear kernel: grid (12,12), 256 threads, 32x32 tile. Also zeroes g_flag.
// ---------------------------------------------------------------------------
__global__ __launch_bounds__(256) void linear_kernel(const float* __restrict__ x1,
                                                     const float* __restrict__ W,
                                                     const float* __restrict__ b) {
    __shared__ float sX[32][33], sW[32][33];
    const int tid = threadIdx.x;
    const int n0 = blockIdx.y * 32, k0 = blockIdx.x * 32;
    if (blockIdx.y == 0 && tid < 32) g_flag[blockIdx.x * 32 + tid] = 0;

    const int ty = tid >> 4, tx = tid & 15;
    float acc[2][2] = {{0.f, 0.f}, {0.f, 0.f}};
    for (int m0 = 0; m0 < N; m0 += 32) {
        const int r = tid >> 3, c4 = (tid & 7) * 4;
        float4 fx = *reinterpret_cast<const float4*>(x1 + (size_t)(n0 + r) * N + m0 + c4);
        sX[r][c4] = fx.x; sX[r][c4 + 1] = fx.y; sX[r][c4 + 2] = fx.z; sX[r][c4 + 3] = fx.w;
        float4 fw = *reinterpret_cast<const float4*>(W + (size_t)(k0 + r) * N + m0 + c4);
        sW[r][c4] = fw.x; sW[r][c4 + 1] = fw.y; sW[r][c4 + 2] = fw.z; sW[r][c4 + 3] = fw.w;
        __syncthreads();
#pragma unroll
        for (int mm = 0; mm < 32; ++mm) {
            float a0 = sX[ty * 2][mm], a1 = sX[ty * 2 + 1][mm];
            float b0 = sW[tx * 2][mm], b1 = sW[tx * 2 + 1][mm];
            acc[0][0] += a0 * b0; acc[0][1] += a0 * b1;
            acc[1][0] += a1 * b0; acc[1][1] += a1 * b1;
        }
        __syncthreads();
    }
#pragma unroll
    for (int r2 = 0; r2 < 2; ++r2)
#pragma unroll
        for (int k2 = 0; k2 < 2; ++k2) {
            int n = n0 + ty * 2 + r2, k = k0 + tx * 2 + k2;
            g_v1p[((size_t)(k >> 4) * N + n) * BS + (k & 15)] =
                __float2bfloat16(acc[r2][k2] + __ldg(b + k));
        }
}

// ---------------------------------------------------------------------------
// Fused convert + attention: 512 threads, 16 warps = 4 row x 4 col groups.
// ---------------------------------------------------------------------------
__global__ __launch_bounds__(512, 1)
void attn_kernel(const float* __restrict__ x2, float* __restrict__ out) {
    extern __shared__ char smem[];
    __shared__ __align__(8) uint64_t s_mbar[3];
    __nv_bfloat16* sQ = reinterpret_cast<__nv_bfloat16*>(smem);
    float* srow = reinterpret_cast<float*>(smem + OFF_SROW);
    float* cs_s = reinterpret_cast<float*>(smem + OFF_CS);

    const int tid = threadIdx.x;
    const int lane = tid & 31;
    const int warp = tid >> 5;
    const int wr = warp & 3;       // rows wr*32..+32
    const int wc = warp >> 2;      // cols wc*96..+96
    const int i = blockIdx.y;
    const int jb = blockIdx.x;
    const int j0 = jb * 128;

    const uint32_t sQu = smem_u32(smem);
    const uint32_t sBu = sQu + OFF_BUF;
    uint32_t mb[3];
#pragma unroll
    for (int q = 0; q < 3; ++q) mb[q] = smem_u32(&s_mbar[q]);

    const int rowA = (lane & 7) + ((lane >> 3) & 1) * 8;
    const int colA = (lane >> 4) * 8;
    const uint32_t aBase = sQu + ((wr * 32 + rowA) * QS + colA) * 2;

    const int rowB = (lane & 7) + ((lane >> 4) & 1) * 8;
    const int colB = ((lane >> 3) & 1) * 8;
    const uint32_t bBase1 = sBu + (rowB * BS + colB) * 2;

    const int rowV = (lane & 7) + ((lane >> 3) & 1) * 8;
    const int colV = ((lane >> 4) & 1) * 8;
    const uint32_t bBase2 = sBu + (rowV * VS + colV) * 2;

    // convert-piece geometry: each thread owns (row = tid>>2, col4 = tid&3)
    const int cvRow = tid >> 2;
    const int cvC4 = (tid & 3) * 4;
    const float* xsrc = x2 + ((size_t)i * N + j0) * N;
    __nv_bfloat16* img = g_xp + ((size_t)i * N + j0) * QS;

    // ---- init mbarriers, kick off v1 chunks 0,1; zero colsum ----
    if (tid == 0) {
#pragma unroll
        for (int q = 0; q < 3; ++q) mbar_init(mb[q], 1);
    }
    if (tid < 384) cs_s[tid] = 0.0f;
    __syncthreads();
    const char* v1src = reinterpret_cast<const char*>(g_v1p);
    if (tid == 0) {
        mbar_expect_tx(mb[0], BUF_B);
        bulk_cp(sBu, v1src, BUF_B, mb[0]);
        mbar_expect_tx(mb[1], BUF_B);
        bulk_cp(sBu + BUF_B, v1src + BUF_B, BUF_B, mb[1]);
    }

    // ---- convert piece macro-equivalent (chunk cc: columns cc*16 + cvC4) ----
    auto convert_piece = [&](int cc) {
        const int col = cc * 16 + cvC4;
        float4 f = __ldg(reinterpret_cast<const float4*>(xsrc + (size_t)cvRow * N + col));
        uint2 u = make_uint2(bf2_pack(f.x, f.y), bf2_pack(f.z, f.w));
        *reinterpret_cast<uint2*>(img + (size_t)cvRow * QS + col) = u;
        *reinterpret_cast<uint2*>(sQ + cvRow * QS + col) = u;
        // butterfly over the 8 row-threads sharing (lane&3)
#pragma unroll
        for (int o = 4; o <= 16; o <<= 1) {
            f.x += __shfl_xor_sync(0xffffffffu, f.x, o);
            f.y += __shfl_xor_sync(0xffffffffu, f.y, o);
            f.z += __shfl_xor_sync(0xffffffffu, f.z, o);
            f.w += __shfl_xor_sync(0xffffffffu, f.w, o);
        }
        if (lane < 4) {
            float* cp = cs_s + col;
            atomicAdd(cp + 0, f.x);
            atomicAdd(cp + 1, f.y);
            atomicAdd(cp + 2, f.z);
            atomicAdd(cp + 3, f.w);
        }
    };

    // head: convert chunks 0,1 (consumed by GEMM1 iterations 0,1)
    convert_piece(0);
    convert_piece(1);

    float acc[2][12][4];
#pragma unroll
    for (int ma = 0; ma < 2; ++ma)
#pragma unroll
        for (int na = 0; na < 12; ++na)
#pragma unroll
            for (int r = 0; r < 4; ++r) acc[ma][na][r] = 0.0f;

    // =================== GEMM1: S = Q @ v1^T (+ pipelined convert) ===================
    for (int kc = 0; kc < 24; ++kc) {
        const int buf = kc % 3;
        mbar_wait(mb[buf], (kc / 3) & 1);
        __syncthreads();
        if (kc + 2 < 24 && tid == 0) {
            const int nb = (kc + 2) % 3;
            mbar_expect_tx(mb[nb], BUF_B);
            bulk_cp(sBu + nb * BUF_B, v1src + (size_t)(kc + 2) * BUF_B, BUF_B, mb[nb]);
        }
        uint32_t a[2][4];
#pragma unroll
        for (int ma = 0; ma < 2; ++ma)
            ldm4(a[ma], aBase + (ma * 16 * QS + kc * 16) * 2);
        const uint32_t bb = bBase1 + buf * BUF_B + wc * 96 * 48;
        uint32_t bfr[2][4];
        ldm4(bfr[0], bb);
#pragma unroll
        for (int nbx = 0; nbx < 6; ++nbx) {
            if (nbx < 5) ldm4(bfr[(nbx + 1) & 1], bb + (nbx + 1) * 16 * 48);
            const uint32_t* bc = bfr[nbx & 1];
#pragma unroll
            for (int ma = 0; ma < 2; ++ma) {
                mma16816(acc[ma][2 * nbx], a[ma], bc[0], bc[1]);
                mma16816(acc[ma][2 * nbx + 1], a[ma], bc[2], bc[3]);
            }
        }
        // pipelined convert of chunk kc+2 (ready before iteration kc+2's sync)
        if (kc < 22) convert_piece(kc + 2);
    }

    // ---- publish: colsum partial + image done ----
    __syncthreads();
    if (tid < 384) g_cs3[((size_t)(i * 3 + jb)) * N + tid] = cs_s[tid];
    __threadfence();
    __syncthreads();
    if (tid == 0) atomicAdd(&g_flag[i], 1);

    // =================== softmax: delta = e/s - 1/N (bf16 into sQ) ===================
    float rs[2][2] = {{0.f, 0.f}, {0.f, 0.f}};
#pragma unroll
    for (int ma = 0; ma < 2; ++ma)
#pragma unroll
        for (int na = 0; na < 12; ++na) {
            float* d = acc[ma][na];
            d[0] = __expf(d[0] * SCALE_INV);
            d[1] = __expf(d[1] * SCALE_INV);
            d[2] = __expf(d[2] * SCALE_INV);
            d[3] = __expf(d[3] * SCALE_INV);
            rs[ma][0] += d[0] + d[1];
            rs[ma][1] += d[2] + d[3];
        }
#pragma unroll
    for (int ma = 0; ma < 2; ++ma)
#pragma unroll
        for (int h = 0; h < 2; ++h) {
            rs[ma][h] += __shfl_xor_sync(0xffffffffu, rs[ma][h], 1);
            rs[ma][h] += __shfl_xor_sync(0xffffffffu, rs[ma][h], 2);
        }
    if ((lane & 3) == 0) {
#pragma unroll
        for (int ma = 0; ma < 2; ++ma)
#pragma unroll
            for (int h = 0; h < 2; ++h)
                srow[wc * 128 + wr * 32 + ma * 16 + h * 8 + (lane >> 2)] = rs[ma][h];
    }
    __syncthreads();
    float invs[2][2];
#pragma unroll
    for (int ma = 0; ma < 2; ++ma)
#pragma unroll
        for (int h = 0; h < 2; ++h) {
            int r = wr * 32 + ma * 16 + h * 8 + (lane >> 2);
            invs[ma][h] = 1.0f / (srow[r] + srow[128 + r] + srow[256 + r] + srow[384 + r]);
        }
#pragma unroll
    for (int ma = 0; ma < 2; ++ma)
#pragma unroll
        for (int na = 0; na < 12; ++na) {
            int r = wr * 32 + ma * 16 + (lane >> 2);
            int c = wc * 96 + (na >> 1) * 16 + (na & 1) * 8 + (lane & 3) * 2;
            float* d = acc[ma][na];
            *reinterpret_cast<uint32_t*>(sQ + r * QS + c) =
                bf2_pack(d[0] * invs[ma][0] - INV_N, d[1] * invs[ma][0] - INV_N);
            *reinterpret_cast<uint32_t*>(sQ + (r + 8) * QS + c) =
                bf2_pack(d[2] * invs[ma][1] - INV_N, d[3] * invs[ma][1] - INV_N);
        }
    __syncthreads();

    // ---- wait for siblings, kick off V chunks 0,1, assemble colsum ----
    if (tid == 0) {
        while (atomicAdd(&g_flag[i], 0) < 3) {}
    }
    __syncthreads();
    const char* vsrc = reinterpret_cast<const char*>(g_xp + (size_t)i * N * QS);
    if (tid == 0) {
        mbar_expect_tx(mb[0], 16 * VS * 2);
        bulk_cp(sBu, vsrc, 16 * VS * 2, mb[0]);
        mbar_expect_tx(mb[1], 16 * VS * 2);
        bulk_cp(sBu + BUF_B, vsrc + (size_t)16 * VS * 2, 16 * VS * 2, mb[1]);
    }
    if (tid < 384) {
        float s0 = 0.f;
#pragma unroll
        for (int p = 0; p < 3; ++p) s0 += __ldg(g_cs3 + ((size_t)(i * 3 + p)) * N + tid);
        cs_s[tid] = s0;
    }

    // =================== GEMM2: corr = delta @ V ===================
#pragma unroll
    for (int ma = 0; ma < 2; ++ma)
#pragma unroll
        for (int na = 0; na < 12; ++na)
#pragma unroll
            for (int r = 0; r < 4; ++r) acc[ma][na][r] = 0.0f;

    for (int nc = 0; nc < 24; ++nc) {
        const int buf = nc % 3;
        mbar_wait(mb[buf], (nc / 3) & 1);
        __syncthreads();
        if (nc + 2 < 24 && tid == 0) {
            const int nb = (nc + 2) % 3;
            mbar_expect_tx(mb[nb], 16 * VS * 2);
            bulk_cp(sBu + nb * BUF_B, vsrc + (size_t)(nc + 2) * 16 * VS * 2,
                    16 * VS * 2, mb[nb]);
        }
        uint32_t a[2][4];
#pragma unroll
        for (int ma = 0; ma < 2; ++ma)
            ldm4(a[ma], aBase + (ma * 16 * QS + nc * 16) * 2);
        const uint32_t bb = bBase2 + buf * BUF_B + wc * 96 * 2;
        uint32_t bfr[2][4];
        ldm4t(bfr[0], bb);
#pragma unroll
        for (int nbx = 0; nbx < 6; ++nbx) {
            if (nbx < 5) ldm4t(bfr[(nbx + 1) & 1], bb + (nbx + 1) * 16 * 2);
            const uint32_t* bc = bfr[nbx & 1];
#pragma unroll
            for (int ma = 0; ma < 2; ++ma) {
                mma16816(acc[ma][2 * nbx], a[ma], bc[0], bc[1]);
                mma16816(acc[ma][2 * nbx + 1], a[ma], bc[2], bc[3]);
            }
        }
    }

    // =================== epilogue: out = corr + colsum/384 ===================
#pragma unroll
    for (int ma = 0; ma < 2; ++ma)
#pragma unroll
        for (int nbx = 0; nbx < 6; ++nbx)
#pragma unroll
            for (int ct = 0; ct < 2; ++ct) {
                int na = nbx * 2 + ct;
                int r = j0 + wr * 32 + ma * 16 + (lane >> 2);
                int c = wc * 96 + nbx * 16 + ct * 8 + (lane & 3) * 2;
                float cs0 = cs_s[c] * INV_N;
                float cs1 = cs_s[c + 1] * INV_N;
                float* d = acc[ma][na];
                float2 o0 = make_float2(d[0] + cs0, d[1] + cs1);
                float2 o1 = make_float2(d[2] + cs0, d[3] + cs1);
                *reinterpret_cast<float2*>(out + ((size_t)i * N + r) * N + c) = o0;
                *reinterpret_cast<float2*>(out + ((size_t)i * N + r + 8) * N + c) = o1;
            }
}

// ---------------------------------------------------------------------------
extern "C" void kernel_launch(void* const* d_in, const int* in_sizes, int n_in,
                              void* d_out, int out_size) {
    const float* x1 = (const float*)d_in[0];
    const float* x2 = (const float*)d_in[1];
    const float* W  = (const float*)d_in[2];
    const float* b  = (const float*)d_in[3];
    float* out = (float*)d_out;
    (void)in_sizes; (void)n_in; (void)out_size;

    {
        dim3 g(12, 12);
        linear_kernel<<<g, 256>>>(x1, W, b);
    }
    {
        cudaFuncSetAttribute(attn_kernel, cudaFuncAttributeMaxDynamicSharedMemorySize, SMEM_ATTN);
        dim3 g(3, 384);
        attn_kernel<<<g, 512, SMEM_ATTN>>>(x2, out);
    }
}